// round 2
// baseline (speedup 1.0000x reference)
#include <cuda_runtime.h>
#include <cuda_bf16.h>

#define EPS_SIGN 1e-8f
#define EPS_NORM 1e-9f

// One thread handles 4 consecutive edges:
//   - int4 loads of src/dst (coalesced, vectorized)
//   - xyz gathers hit L2 (table is 1.2 MB << 126 MB L2)
//   - float4 store of dis, 3x float4 store of vec (48 B/thread, 16 B aligned)
__global__ __launch_bounds__(256)
void edge_min_image_kernel(const float* __restrict__ xyz,
                           const int*   __restrict__ src,
                           const int*   __restrict__ dst,
                           const float* __restrict__ cell,
                           float* __restrict__ out_dis,
                           float* __restrict__ out_vec,
                           int E)
{
    const float cx = __ldg(&cell[0]);
    const float cy = __ldg(&cell[1]);
    const float cz = __ldg(&cell[2]);

    int t  = blockIdx.x * blockDim.x + threadIdx.x;
    int e0 = t * 4;
    if (e0 >= E) return;

    int s[4], d[4];
    bool full = (e0 + 3 < E);
    if (full) {
        int4 s4 = *reinterpret_cast<const int4*>(src + e0);
        int4 d4 = *reinterpret_cast<const int4*>(dst + e0);
        s[0] = s4.x; s[1] = s4.y; s[2] = s4.z; s[3] = s4.w;
        d[0] = d4.x; d[1] = d4.y; d[2] = d4.z; d[3] = d4.w;
    } else {
        #pragma unroll
        for (int i = 0; i < 4; i++) {
            int e = e0 + i;
            s[i] = (e < E) ? src[e] : 0;
            d[i] = (e < E) ? dst[e] : 0;
        }
    }

    float dis4[4];
    float vec[12];

    #pragma unroll
    for (int i = 0; i < 4; i++) {
        const float* ps = xyz + 3 * s[i];
        const float* pd = xyz + 3 * d[i];
        float dx = __ldg(ps + 0) - __ldg(pd + 0);
        float dy = __ldg(ps + 1) - __ldg(pd + 1);
        float dz = __ldg(ps + 2) - __ldg(pd + 2);

        float ax = fabsf(dx), ay = fabsf(dy), az = fabsf(dz);

        // min-image component
        float mx = fminf(cx - ax, ax);
        float my = fminf(cy - ay, ay);
        float mz = fminf(cz - az, az);

        // mask2: +1 if min-image kept the original magnitude, else -1
        float k2x = (fabsf(mx) == ax) ? 1.0f : -1.0f;
        float k2y = (fabsf(my) == ay) ? 1.0f : -1.0f;
        float k2z = (fabsf(mz) == az) ? 1.0f : -1.0f;

        // epsilon-stabilized sign of the original displacement (exact ±1)
        float tx = dx + EPS_SIGN, ty = dy + EPS_SIGN, tz = dz + EPS_SIGN;
        float sx = tx / fabsf(tx);
        float sy = ty / fabsf(ty);
        float sz = tz / fabsf(tz);

        vec[3*i + 0] = mx * (k2x * sx);
        vec[3*i + 1] = my * (k2y * sy);
        vec[3*i + 2] = mz * (k2z * sz);

        // norm of the ORIGINAL (non-min-image) vector, + eps
        float ex = dx + EPS_NORM, ey = dy + EPS_NORM, ez = dz + EPS_NORM;
        dis4[i] = sqrtf(ex*ex + ey*ey + ez*ez);
    }

    if (full) {
        *reinterpret_cast<float4*>(out_dis + e0) =
            make_float4(dis4[0], dis4[1], dis4[2], dis4[3]);
        float4* vp = reinterpret_cast<float4*>(out_vec + 3 * e0); // 48B, 16B-aligned
        vp[0] = make_float4(vec[0], vec[1],  vec[2],  vec[3]);
        vp[1] = make_float4(vec[4], vec[5],  vec[6],  vec[7]);
        vp[2] = make_float4(vec[8], vec[9],  vec[10], vec[11]);
    } else {
        #pragma unroll
        for (int i = 0; i < 4; i++) {
            int e = e0 + i;
            if (e < E) {
                out_dis[e] = dis4[i];
                out_vec[3*e + 0] = vec[3*i + 0];
                out_vec[3*e + 1] = vec[3*i + 1];
                out_vec[3*e + 2] = vec[3*i + 2];
            }
        }
    }
}

extern "C" void kernel_launch(void* const* d_in, const int* in_sizes, int n_in,
                              void* d_out, int out_size)
{
    const float* xyz  = (const float*)d_in[0];
    const int*   src  = (const int*)  d_in[1];
    const int*   dst  = (const int*)  d_in[2];
    const float* cell = (const float*)d_in[3];

    int E = in_sizes[1];  // number of edges (src length)

    float* out_dis = (float*)d_out;      // [E]
    float* out_vec = out_dis + E;        // [E,3] row-major

    int threads = 256;
    int groups  = (E + 3) / 4;
    int blocks  = (groups + threads - 1) / threads;
    edge_min_image_kernel<<<blocks, threads>>>(xyz, src, dst, cell,
                                               out_dis, out_vec, E);
}

// round 4
// speedup vs baseline: 1.2660x; 1.2660x over previous
#include <cuda_runtime.h>
#include <cuda_bf16.h>

#define EPS_SIGN 1e-8f
#define EPS_NORM 1e-9f

// Scratch: padded xyz as float4 so each node gather is ONE LDG.128
// (1 L1 wavefront stream instead of ~3 for a 12B row).
// __device__ global = the sanctioned scratch mechanism (no allocation).
#define XYZ4_CAP 131072
__device__ float4 g_xyz4[XYZ4_CAP];

__global__ __launch_bounds__(256)
void repack_xyz_kernel(const float* __restrict__ xyz, int N)
{
    for (int i = blockIdx.x * blockDim.x + threadIdx.x;
         i < N;
         i += gridDim.x * blockDim.x)
    {
        float x = xyz[3*i + 0];
        float y = xyz[3*i + 1];
        float z = xyz[3*i + 2];
        g_xyz4[i] = make_float4(x, y, z, 0.0f);
    }
}

__global__ __launch_bounds__(256)
void edge_min_image_kernel(const int*   __restrict__ src,
                           const int*   __restrict__ dst,
                           const float* __restrict__ cell,
                           float* __restrict__ out_dis,
                           float* __restrict__ out_vec,
                           int E)
{
    const float cx = __ldg(&cell[0]);
    const float cy = __ldg(&cell[1]);
    const float cz = __ldg(&cell[2]);

    int t  = blockIdx.x * blockDim.x + threadIdx.x;
    int e0 = t * 4;
    if (e0 >= E) return;

    int s[4], d[4];
    bool full = (e0 + 3 < E);
    if (full) {
        int4 s4 = *reinterpret_cast<const int4*>(src + e0);
        int4 d4 = *reinterpret_cast<const int4*>(dst + e0);
        s[0] = s4.x; s[1] = s4.y; s[2] = s4.z; s[3] = s4.w;
        d[0] = d4.x; d[1] = d4.y; d[2] = d4.z; d[3] = d4.w;
    } else {
        #pragma unroll
        for (int i = 0; i < 4; i++) {
            int e = e0 + i;
            s[i] = (e < E) ? src[e] : 0;
            d[i] = (e < E) ? dst[e] : 0;
        }
    }

    float dis4[4];
    float vec[12];

    #pragma unroll
    for (int i = 0; i < 4; i++) {
        float4 a = g_xyz4[s[i]];   // single LDG.128 each
        float4 b = g_xyz4[d[i]];

        float dx = a.x - b.x;
        float dy = a.y - b.y;
        float dz = a.z - b.z;

        float ax = fabsf(dx), ay = fabsf(dy), az = fabsf(dz);

        // min-image component
        float mx = fminf(cx - ax, ax);
        float my = fminf(cy - ay, ay);
        float mz = fminf(cz - az, az);

        // mask2: +1 if min-image kept the original magnitude, else -1
        float k2x = (fabsf(mx) == ax) ? 1.0f : -1.0f;
        float k2y = (fabsf(my) == ay) ? 1.0f : -1.0f;
        float k2z = (fabsf(mz) == az) ? 1.0f : -1.0f;

        // sign of (d + eps): exact +-1 via compare-select (matches t/|t|)
        float sx = (dx + EPS_SIGN >= 0.0f) ? 1.0f : -1.0f;
        float sy = (dy + EPS_SIGN >= 0.0f) ? 1.0f : -1.0f;
        float sz = (dz + EPS_SIGN >= 0.0f) ? 1.0f : -1.0f;

        vec[3*i + 0] = mx * (k2x * sx);
        vec[3*i + 1] = my * (k2y * sy);
        vec[3*i + 2] = mz * (k2z * sz);

        // norm of the ORIGINAL (non-min-image) vector, + eps
        float ex = dx + EPS_NORM, ey = dy + EPS_NORM, ez = dz + EPS_NORM;
        dis4[i] = sqrtf(ex*ex + ey*ey + ez*ez);
    }

    if (full) {
        *reinterpret_cast<float4*>(out_dis + e0) =
            make_float4(dis4[0], dis4[1], dis4[2], dis4[3]);
        float4* vp = reinterpret_cast<float4*>(out_vec + 3 * e0); // 48B, 16B-aligned
        vp[0] = make_float4(vec[0], vec[1],  vec[2],  vec[3]);
        vp[1] = make_float4(vec[4], vec[5],  vec[6],  vec[7]);
        vp[2] = make_float4(vec[8], vec[9],  vec[10], vec[11]);
    } else {
        #pragma unroll
        for (int i = 0; i < 4; i++) {
            int e = e0 + i;
            if (e < E) {
                out_dis[e] = dis4[i];
                out_vec[3*e + 0] = vec[3*i + 0];
                out_vec[3*e + 1] = vec[3*i + 1];
                out_vec[3*e + 2] = vec[3*i + 2];
            }
        }
    }
}

// Fallback (N > scratch capacity): scalar-gather path, always correct.
__global__ __launch_bounds__(256)
void edge_min_image_fallback(const float* __restrict__ xyz,
                             const int*   __restrict__ src,
                             const int*   __restrict__ dst,
                             const float* __restrict__ cell,
                             float* __restrict__ out_dis,
                             float* __restrict__ out_vec,
                             int E)
{
    const float cx = __ldg(&cell[0]);
    const float cy = __ldg(&cell[1]);
    const float cz = __ldg(&cell[2]);

    int e = blockIdx.x * blockDim.x + threadIdx.x;
    if (e >= E) return;

    int si = src[e], di = dst[e];
    float dx = xyz[3*si+0] - xyz[3*di+0];
    float dy = xyz[3*si+1] - xyz[3*di+1];
    float dz = xyz[3*si+2] - xyz[3*di+2];

    float ax = fabsf(dx), ay = fabsf(dy), az = fabsf(dz);
    float mx = fminf(cx - ax, ax);
    float my = fminf(cy - ay, ay);
    float mz = fminf(cz - az, az);
    float k2x = (fabsf(mx) == ax) ? 1.0f : -1.0f;
    float k2y = (fabsf(my) == ay) ? 1.0f : -1.0f;
    float k2z = (fabsf(mz) == az) ? 1.0f : -1.0f;
    float sx = (dx + EPS_SIGN >= 0.0f) ? 1.0f : -1.0f;
    float sy = (dy + EPS_SIGN >= 0.0f) ? 1.0f : -1.0f;
    float sz = (dz + EPS_SIGN >= 0.0f) ? 1.0f : -1.0f;

    out_vec[3*e+0] = mx * (k2x * sx);
    out_vec[3*e+1] = my * (k2y * sy);
    out_vec[3*e+2] = mz * (k2z * sz);

    float ex = dx + EPS_NORM, ey = dy + EPS_NORM, ez = dz + EPS_NORM;
    out_dis[e] = sqrtf(ex*ex + ey*ey + ez*ez);
}

extern "C" void kernel_launch(void* const* d_in, const int* in_sizes, int n_in,
                              void* d_out, int out_size)
{
    const float* xyz  = (const float*)d_in[0];
    const int*   src  = (const int*)  d_in[1];
    const int*   dst  = (const int*)  d_in[2];
    const float* cell = (const float*)d_in[3];

    int N = in_sizes[0] / 3;   // xyz rows
    int E = in_sizes[1];       // number of edges

    float* out_dis = (float*)d_out;   // [E]
    float* out_vec = out_dis + E;     // [E,3] row-major

    const int t = 256;
    if (N <= XYZ4_CAP) {
        int rblocks = (N + t - 1) / t;
        if (rblocks > 1184) rblocks = 1184;  // grid-stride covers the rest
        repack_xyz_kernel<<<rblocks, t>>>(xyz, N);
        int groups = (E + 3) / 4;
        edge_min_image_kernel<<<(groups + t - 1) / t, t>>>(src, dst, cell,
                                                           out_dis, out_vec, E);
    } else {
        edge_min_image_fallback<<<(E + t - 1) / t, t>>>(xyz, src, dst, cell,
                                                        out_dis, out_vec, E);
    }
}